// round 3
// baseline (speedup 1.0000x reference)
#include <cuda_runtime.h>

// Problem constants (fixed: B=16, T=1024, D=1024, O=10)
#define BB 16
#define TT 1024
#define DD 1024
#define OO 10

#define CTA 256
#define WARPS 8
#define RPW 8                         // rows per warp
#define RPC (WARPS * RPW)             // 64 rows per CTA
#define KT 128                        // d-tile per stage
#define NKT (DD / KT)                 // 8
#define W_FLOATS (OO * DD)            // 10240
#define STAGE_FLOATS (RPC * KT)       // 8192
#define SMEM_BYTES ((W_FLOATS + 2 * STAGE_FLOATS) * 4)   // 106496

__device__ float g_scores[BB * OO * TT];   // [b][o][t]
__device__ float g_wx[BB * OO * TT];       // softmaxed, [b][o][i]

typedef unsigned long long ull;

__device__ __forceinline__ void ffma2(ull& a, ull x, ull y) {
    asm("fma.rn.f32x2 %0, %1, %2, %0;" : "+l"(a) : "l"(x), "l"(y));
}
__device__ __forceinline__ float hsum(ull v) {
    float lo, hi;
    asm("mov.b64 {%0, %1}, %2;" : "=f"(lo), "=f"(hi) : "l"(v));
    return lo + hi;
}
__device__ __forceinline__ void cp16(unsigned s, const void* g) {
    asm volatile("cp.async.cg.shared.global [%0], [%1], 16;" :: "r"(s), "l"(g));
}
__device__ __forceinline__ void cp_commit() {
    asm volatile("cp.async.commit_group;");
}
__device__ __forceinline__ void cp_wait1() {
    asm volatile("cp.async.wait_group 1;");
}

// ---------------------------------------------------------------------------
// Pipelined GEMV core: 64 rows x 1024 d against Wsrc (10 x 1024).
// Writes packed-f32x2 partials into acc[8][10] (per-lane d-slices).
// ---------------------------------------------------------------------------
__device__ __forceinline__ void gemv_pipeline(const float* __restrict__ rows_base,
                                              const float* __restrict__ Wsrc,
                                              float* smem,
                                              ull (&acc)[RPW][OO]) {
    const int tid = threadIdx.x;
    const int warp = tid >> 5;
    const int lane = tid & 31;

    float* Wsm = smem;
    float* stg = smem + W_FLOATS;

    const unsigned sb_w = (unsigned)__cvta_generic_to_shared(Wsm);
    const unsigned sb_s = (unsigned)__cvta_generic_to_shared(stg);

    // Stage issue: 2048 16B-chunks / 256 threads = 8 per thread
    auto issue_stage = [&](int kt) {
        const unsigned base = sb_s + (kt & 1) * (STAGE_FLOATS * 4);
        #pragma unroll
        for (int t = 0; t < 8; t++) {
            const int j = tid + t * CTA;
            const int r = j >> 5;
            const int c = (j & 31) << 2;
            cp16(base + (unsigned)(r * KT + c) * 4,
                 rows_base + (size_t)r * DD + (size_t)kt * KT + c);
        }
    };

    // Prologue: group0 = W + stage0; group1 = stage1
    #pragma unroll
    for (int t = 0; t < 10; t++) {
        const int j = tid + t * CTA;          // 0..2559 float4 chunks of W
        cp16(sb_w + (unsigned)j * 16, Wsrc + (size_t)j * 4);
    }
    issue_stage(0);
    cp_commit();
    issue_stage(1);
    cp_commit();

    #pragma unroll
    for (int r = 0; r < RPW; r++)
        #pragma unroll
        for (int o = 0; o < OO; o++) acc[r][o] = 0ull;

    for (int kt = 0; kt < NKT; kt++) {
        cp_wait1();               // stage kt (and W) resident
        __syncthreads();

        const int slot = kt & 1;
        const float* sb = stg + slot * STAGE_FLOATS + (warp * RPW) * KT;

        #pragma unroll
        for (int half = 0; half < 2; half++) {
            const int d0 = half * 64 + lane * 2;
            ull lg[RPW];
            #pragma unroll
            for (int r = 0; r < RPW; r++)
                lg[r] = *(const ull*)(sb + r * KT + d0);
            #pragma unroll
            for (int o = 0; o < OO; o++) {
                const ull wv = *(const ull*)(Wsm + o * DD + kt * KT + d0);
                #pragma unroll
                for (int r = 0; r < RPW; r++)
                    ffma2(acc[r][o], lg[r], wv);
            }
        }

        __syncthreads();          // all warps done with slot before refill
        if (kt + 2 < NKT) issue_stage(kt + 2);
        cp_commit();              // always commit to keep group accounting
    }
}

// ---------------------------------------------------------------------------
// Kernel 1: scores[b][o][t] = (logits[b,t,:] . W[o,:] + bias[o]) / OO
// ---------------------------------------------------------------------------
__global__ __launch_bounds__(CTA, 2) void k_scores(const float* __restrict__ logits,
                                                   const float* __restrict__ W,
                                                   const float* __restrict__ bias) {
    extern __shared__ float smem[];
    const int warp = threadIdx.x >> 5;
    const int lane = threadIdx.x & 31;

    ull acc[RPW][OO];
    gemv_pipeline(logits + (size_t)blockIdx.x * RPC * DD, W, smem, acc);

    const int row0 = blockIdx.x * RPC + warp * RPW;
    const int b = row0 / TT;
    const int t0 = row0 % TT;
    #pragma unroll
    for (int r = 0; r < RPW; r++)
        #pragma unroll
        for (int o = 0; o < OO; o++) {
            float v = hsum(acc[r][o]);
            #pragma unroll
            for (int s = 16; s > 0; s >>= 1)
                v += __shfl_xor_sync(0xffffffffu, v, s);
            if (lane == 0)
                g_scores[(b * OO + o) * TT + t0 + r] =
                    (v + bias[o]) * (1.0f / OO);
        }
}

// ---------------------------------------------------------------------------
// Kernel 2: softmax over t for each (b,o). 160 blocks x 256 threads.
// ---------------------------------------------------------------------------
__global__ __launch_bounds__(256) void k_softmax() {
    const int ro = blockIdx.x;
    const int tid = threadIdx.x;
    const float4 v = ((const float4*)&g_scores[ro * TT])[tid];

    __shared__ float red[8];

    float m = fmaxf(fmaxf(v.x, v.y), fmaxf(v.z, v.w));
    #pragma unroll
    for (int s = 16; s > 0; s >>= 1)
        m = fmaxf(m, __shfl_xor_sync(0xffffffffu, m, s));
    if ((tid & 31) == 0) red[tid >> 5] = m;
    __syncthreads();
    float mall = red[0];
    #pragma unroll
    for (int i = 1; i < 8; i++) mall = fmaxf(mall, red[i]);
    __syncthreads();

    float4 e;
    e.x = __expf(v.x - mall);
    e.y = __expf(v.y - mall);
    e.z = __expf(v.z - mall);
    e.w = __expf(v.w - mall);
    float s4 = e.x + e.y + e.z + e.w;
    #pragma unroll
    for (int s = 16; s > 0; s >>= 1)
        s4 += __shfl_xor_sync(0xffffffffu, s4, s);
    if ((tid & 31) == 0) red[tid >> 5] = s4;
    __syncthreads();
    float sall = 0.0f;
    #pragma unroll
    for (int i = 0; i < 8; i++) sall += red[i];

    const float inv = 1.0f / sall;
    float4 w;
    w.x = e.x * inv; w.y = e.y * inv; w.z = e.z * inv; w.w = e.w * inv;
    ((float4*)&g_wx[ro * TT])[tid] = w;
}

// ---------------------------------------------------------------------------
// Kernel 3: out[b][o][t] = sum_i logits[b,t,i] * g_wx[b][o][i]
// ---------------------------------------------------------------------------
__global__ __launch_bounds__(CTA, 2) void k_out(const float* __restrict__ logits,
                                                float* __restrict__ out) {
    extern __shared__ float smem[];
    const int warp = threadIdx.x >> 5;
    const int lane = threadIdx.x & 31;

    const int row0blk = blockIdx.x * RPC;
    const int b = row0blk / TT;                 // 64 rows never cross a batch

    ull acc[RPW][OO];
    gemv_pipeline(logits + (size_t)row0blk * DD, g_wx + (size_t)b * W_FLOATS,
                  smem, acc);

    const int row0 = row0blk + warp * RPW;
    const int t0 = row0 % TT;
    #pragma unroll
    for (int r = 0; r < RPW; r++)
        #pragma unroll
        for (int o = 0; o < OO; o++) {
            float v = hsum(acc[r][o]);
            #pragma unroll
            for (int s = 16; s > 0; s >>= 1)
                v += __shfl_xor_sync(0xffffffffu, v, s);
            if (lane == 0)
                out[(b * OO + o) * TT + t0 + r] = v;
        }
}

// ---------------------------------------------------------------------------
// Launch: inputs per metadata order: logits, decision(unused), W, b
// ---------------------------------------------------------------------------
extern "C" void kernel_launch(void* const* d_in, const int* in_sizes, int n_in,
                              void* d_out, int out_size) {
    const float* logits = (const float*)d_in[0];
    const float* W = (const float*)d_in[2];
    const float* bias = (const float*)d_in[3];
    float* out = (float*)d_out;

    static int attr_done = 0;
    if (!attr_done) {
        cudaFuncSetAttribute(k_scores, cudaFuncAttributeMaxDynamicSharedMemorySize,
                             SMEM_BYTES);
        cudaFuncSetAttribute(k_out, cudaFuncAttributeMaxDynamicSharedMemorySize,
                             SMEM_BYTES);
        attr_done = 1;
    }

    k_scores<<<(BB * TT) / RPC, CTA, SMEM_BYTES>>>(logits, W, bias);
    k_softmax<<<BB * OO, 256>>>();
    k_out<<<(BB * TT) / RPC, CTA, SMEM_BYTES>>>(logits, out);
}

// round 4
// speedup vs baseline: 3.4535x; 3.4535x over previous
#include <cuda_runtime.h>

// Problem constants (fixed: B=16, T=1024, D=1024, O=10)
#define BB 16
#define TT 1024
#define DD 1024
#define OO 10

#define CTA 256
#define WARPS 8
#define RPW 4                          // rows per warp (acc fits 128-reg cap)
#define RPC (WARPS * RPW)              // 32 rows per CTA
#define KT 128                         // d-tile per stage
#define NKT (DD / KT)                  // 8
#define W_FLOATS (OO * DD)             // 10240
#define STAGE_FLOATS (RPC * KT)        // 4096
#define SMEM_BYTES ((W_FLOATS + 2 * STAGE_FLOATS) * 4)   // 73728

__device__ float g_scores[BB * OO * TT];   // [b][o][t]
__device__ float g_wx[BB * OO * TT];       // softmaxed, [b][o][i]

typedef unsigned long long ull;

__device__ __forceinline__ void ffma2(ull& a, ull x, ull y) {
    asm("fma.rn.f32x2 %0, %1, %2, %0;" : "+l"(a) : "l"(x), "l"(y));
}
__device__ __forceinline__ float hsum(ull v) {
    float lo, hi;
    asm("mov.b64 {%0, %1}, %2;" : "=f"(lo), "=f"(hi) : "l"(v));
    return lo + hi;
}
__device__ __forceinline__ void cp16(unsigned s, const void* g) {
    asm volatile("cp.async.cg.shared.global [%0], [%1], 16;" :: "r"(s), "l"(g));
}
__device__ __forceinline__ void cp_commit() {
    asm volatile("cp.async.commit_group;");
}
__device__ __forceinline__ void cp_wait1() {
    asm volatile("cp.async.wait_group 1;");
}

// ---------------------------------------------------------------------------
// Pipelined GEMV core: 32 rows x 1024 d against Wsrc (10 x 1024).
// Packed-f32x2 (over d) partials in acc[4][10].
// ---------------------------------------------------------------------------
__device__ __forceinline__ void gemv_pipeline(const float* __restrict__ rows_base,
                                              const float* __restrict__ Wsrc,
                                              float* smem,
                                              ull (&acc)[RPW][OO]) {
    const int tid = threadIdx.x;
    const int warp = tid >> 5;
    const int lane = tid & 31;

    float* Wsm = smem;
    float* stg = smem + W_FLOATS;

    const unsigned sb_w = (unsigned)__cvta_generic_to_shared(Wsm);
    const unsigned sb_s = (unsigned)__cvta_generic_to_shared(stg);

    // Stage issue: 1024 16B-chunks / 256 threads = 4 per thread
    auto issue_stage = [&](int kt) {
        const unsigned base = sb_s + (kt & 1) * (STAGE_FLOATS * 4);
        #pragma unroll
        for (int t = 0; t < 4; t++) {
            const int j = tid + t * CTA;          // 0..1023
            const int r = j >> 5;                 // 32 chunks per row
            const int c = (j & 31) << 2;
            cp16(base + (unsigned)(r * KT + c) * 4,
                 rows_base + (size_t)r * DD + (size_t)kt * KT + c);
        }
    };

    // Prologue: group0 = W + stage0; group1 = stage1
    #pragma unroll
    for (int t = 0; t < 10; t++) {
        const int j = tid + t * CTA;              // 2560 float4 chunks of W
        cp16(sb_w + (unsigned)j * 16, Wsrc + (size_t)j * 4);
    }
    issue_stage(0);
    cp_commit();
    issue_stage(1);
    cp_commit();

    #pragma unroll
    for (int r = 0; r < RPW; r++)
        #pragma unroll
        for (int o = 0; o < OO; o++) acc[r][o] = 0ull;

    for (int kt = 0; kt < NKT; kt++) {
        cp_wait1();                // stage kt (and W) resident
        __syncthreads();

        const int slot = kt & 1;
        const float* sb = stg + slot * STAGE_FLOATS + (warp * RPW) * KT + lane * 4;
        const float* wb = Wsm + kt * KT + lane * 4;

        ulonglong2 lg[RPW];
        #pragma unroll
        for (int r = 0; r < RPW; r++)
            lg[r] = *(const ulonglong2*)(sb + r * KT);

        #pragma unroll
        for (int o = 0; o < OO; o++) {
            const ulonglong2 w2 = *(const ulonglong2*)(wb + o * DD);
            #pragma unroll
            for (int r = 0; r < RPW; r++) {
                ffma2(acc[r][o], lg[r].x, w2.x);
                ffma2(acc[r][o], lg[r].y, w2.y);
            }
        }

        __syncthreads();           // all warps done with slot before refill
        if (kt + 2 < NKT) issue_stage(kt + 2);
        cp_commit();               // keep group accounting uniform
    }
}

// Shared epilogue: reduce 40 partials across warp, lane0 writes.
__device__ __forceinline__ void reduce_store(ull (&acc)[RPW][OO], int lane,
                                             float* __restrict__ dst,  // [o][t] base
                                             int t0, float scale,
                                             const float* __restrict__ bias) {
    #pragma unroll
    for (int r = 0; r < RPW; r++)
        #pragma unroll
        for (int o = 0; o < OO; o++) {
            float v = hsum(acc[r][o]);
            #pragma unroll
            for (int s = 16; s > 0; s >>= 1)
                v += __shfl_xor_sync(0xffffffffu, v, s);
            if (lane == 0) {
                if (bias) v = (v + bias[o]) * scale;
                dst[o * TT + t0 + r] = v;
            }
        }
}

// ---------------------------------------------------------------------------
// Kernel 1: scores[b][o][t] = (logits[b,t,:] . W[o,:] + bias[o]) / OO
// ---------------------------------------------------------------------------
__global__ __launch_bounds__(CTA, 2) void k_scores(const float* __restrict__ logits,
                                                   const float* __restrict__ W,
                                                   const float* __restrict__ bias) {
    extern __shared__ float smem[];
    const int warp = threadIdx.x >> 5;
    const int lane = threadIdx.x & 31;

    ull acc[RPW][OO];
    gemv_pipeline(logits + (size_t)blockIdx.x * RPC * DD, W, smem, acc);

    const int row0 = blockIdx.x * RPC + warp * RPW;
    const int b = row0 / TT;
    reduce_store(acc, lane, g_scores + b * OO * TT, row0 % TT,
                 1.0f / OO, bias);
}

// ---------------------------------------------------------------------------
// Kernel 2: softmax over t for each (b,o). 160 blocks x 256 threads.
// ---------------------------------------------------------------------------
__global__ __launch_bounds__(256) void k_softmax() {
    const int ro = blockIdx.x;
    const int tid = threadIdx.x;
    const float4 v = ((const float4*)&g_scores[ro * TT])[tid];

    __shared__ float red[8];

    float m = fmaxf(fmaxf(v.x, v.y), fmaxf(v.z, v.w));
    #pragma unroll
    for (int s = 16; s > 0; s >>= 1)
        m = fmaxf(m, __shfl_xor_sync(0xffffffffu, m, s));
    if ((tid & 31) == 0) red[tid >> 5] = m;
    __syncthreads();
    float mall = red[0];
    #pragma unroll
    for (int i = 1; i < 8; i++) mall = fmaxf(mall, red[i]);
    __syncthreads();

    float4 e;
    e.x = __expf(v.x - mall);
    e.y = __expf(v.y - mall);
    e.z = __expf(v.z - mall);
    e.w = __expf(v.w - mall);
    float s4 = e.x + e.y + e.z + e.w;
    #pragma unroll
    for (int s = 16; s > 0; s >>= 1)
        s4 += __shfl_xor_sync(0xffffffffu, s4, s);
    if ((tid & 31) == 0) red[tid >> 5] = s4;
    __syncthreads();
    float sall = 0.0f;
    #pragma unroll
    for (int i = 0; i < 8; i++) sall += red[i];

    const float inv = 1.0f / sall;
    float4 w;
    w.x = e.x * inv; w.y = e.y * inv; w.z = e.z * inv; w.w = e.w * inv;
    ((float4*)&g_wx[ro * TT])[tid] = w;
}

// ---------------------------------------------------------------------------
// Kernel 3: out[b][o][t] = sum_i logits[b,t,i] * g_wx[b][o][i]
// ---------------------------------------------------------------------------
__global__ __launch_bounds__(CTA, 2) void k_out(const float* __restrict__ logits,
                                                float* __restrict__ out) {
    extern __shared__ float smem[];
    const int warp = threadIdx.x >> 5;
    const int lane = threadIdx.x & 31;

    const int row0blk = blockIdx.x * RPC;
    const int b = row0blk / TT;               // 32 rows never cross a batch

    ull acc[RPW][OO];
    gemv_pipeline(logits + (size_t)row0blk * DD, g_wx + (size_t)b * W_FLOATS,
                  smem, acc);

    const int row0 = row0blk + warp * RPW;
    reduce_store(acc, lane, out + b * OO * TT, row0 % TT, 1.0f, nullptr);
}

// ---------------------------------------------------------------------------
// Launch: inputs per metadata order: logits, decision(unused), W, b
// ---------------------------------------------------------------------------
extern "C" void kernel_launch(void* const* d_in, const int* in_sizes, int n_in,
                              void* d_out, int out_size) {
    const float* logits = (const float*)d_in[0];
    const float* W = (const float*)d_in[2];
    const float* bias = (const float*)d_in[3];
    float* out = (float*)d_out;

    cudaFuncSetAttribute(k_scores, cudaFuncAttributeMaxDynamicSharedMemorySize,
                         SMEM_BYTES);
    cudaFuncSetAttribute(k_out, cudaFuncAttributeMaxDynamicSharedMemorySize,
                         SMEM_BYTES);

    k_scores<<<(BB * TT) / RPC, CTA, SMEM_BYTES>>>(logits, W, bias);
    k_softmax<<<BB * OO, 256>>>();
    k_out<<<(BB * TT) / RPC, CTA, SMEM_BYTES>>>(logits, out);
}

// round 5
// speedup vs baseline: 5.0977x; 1.4761x over previous
#include <cuda_runtime.h>

// Problem constants (fixed: B=16, T=1024, D=1024, O=10)
#define BB 16
#define TT 1024
#define DD 1024
#define OO 10

#define CTA 256
#define WARPS 8
#define RPW 4                     // rows per warp
#define RPC (WARPS * RPW)         // 32 rows per CTA
#define KT 128                    // d per iteration (4 floats per lane)
#define NKT (DD / KT)             // 8
#define W_FLOATS (OO * DD)        // 10240 floats = 40 KB static smem

__device__ float g_scores[BB * OO * TT];   // [b][o][t]
__device__ float g_wx[BB * OO * TT];       // softmaxed, [b][o][i]

typedef unsigned long long ull;

__device__ __forceinline__ void ffma2(ull& a, ull x, ull y) {
    asm("fma.rn.f32x2 %0, %1, %2, %0;" : "+l"(a) : "l"(x), "l"(y));
}
__device__ __forceinline__ float hsum(ull v) {
    float lo, hi;
    asm("mov.b64 {%0, %1}, %2;" : "=f"(lo), "=f"(hi) : "l"(v));
    return lo + hi;
}

// ---------------------------------------------------------------------------
// GEMV body: 4 rows x 1024 d (per warp) against Wsm (10 x 1024 in smem).
// Direct LDG with distance-1 double-buffered prefetch; packed f32x2 FMA.
// ---------------------------------------------------------------------------
__device__ __forceinline__ void gemv_body(const float* __restrict__ rbase,
                                          const float* __restrict__ wbase,
                                          ull (&acc)[RPW][OO]) {
    #pragma unroll
    for (int r = 0; r < RPW; r++)
        #pragma unroll
        for (int o = 0; o < OO; o++) acc[r][o] = 0ull;

    ulonglong2 cur[RPW], nxt[RPW];
    #pragma unroll
    for (int r = 0; r < RPW; r++)
        cur[r] = *(const ulonglong2*)(rbase + r * DD);

    #pragma unroll
    for (int kt = 0; kt < NKT; kt++) {
        if (kt + 1 < NKT) {
            #pragma unroll
            for (int r = 0; r < RPW; r++)
                nxt[r] = *(const ulonglong2*)(rbase + r * DD + (kt + 1) * KT);
        }
        #pragma unroll
        for (int o = 0; o < OO; o++) {
            const ulonglong2 w2 = *(const ulonglong2*)(wbase + o * DD + kt * KT);
            #pragma unroll
            for (int r = 0; r < RPW; r++) {
                ffma2(acc[r][o], cur[r].x, w2.x);
                ffma2(acc[r][o], cur[r].y, w2.y);
            }
        }
        #pragma unroll
        for (int r = 0; r < RPW; r++) cur[r] = nxt[r];
    }
}

// Reduce 40 partials across warp; lane0 writes [o][t]-layout results.
__device__ __forceinline__ void reduce_store(ull (&acc)[RPW][OO], int lane,
                                             float* __restrict__ dst,
                                             int t0, float scale,
                                             const float* __restrict__ bias) {
    #pragma unroll
    for (int r = 0; r < RPW; r++)
        #pragma unroll
        for (int o = 0; o < OO; o++) {
            float v = hsum(acc[r][o]);
            #pragma unroll
            for (int s = 16; s > 0; s >>= 1)
                v += __shfl_xor_sync(0xffffffffu, v, s);
            if (lane == 0) {
                if (bias) v = (v + __ldg(&bias[o])) * scale;
                dst[o * TT + t0 + r] = v;
            }
        }
}

// ---------------------------------------------------------------------------
// Kernel 1: scores[b][o][t] = (logits[b,t,:] . W[o,:] + bias[o]) / OO
// Grid 512 x 256. 32 rows/CTA, W loaded once per CTA.
// ---------------------------------------------------------------------------
__global__ __launch_bounds__(CTA, 2) void k_scores(const float* __restrict__ logits,
                                                   const float* __restrict__ W,
                                                   const float* __restrict__ bias) {
    __shared__ float Wsm[W_FLOATS];   // 40 KB static
    {
        const float4* Wv = (const float4*)W;
        float4* Ws = (float4*)Wsm;
        #pragma unroll
        for (int t = 0; t < 10; t++)
            Ws[threadIdx.x + t * CTA] = Wv[threadIdx.x + t * CTA];
    }
    __syncthreads();

    const int warp = threadIdx.x >> 5;
    const int lane = threadIdx.x & 31;
    const int row0 = blockIdx.x * RPC + warp * RPW;

    ull acc[RPW][OO];
    gemv_body(logits + (size_t)row0 * DD + lane * 4, Wsm + lane * 4, acc);

    const int b = row0 / TT;
    reduce_store(acc, lane, g_scores + b * OO * TT, row0 % TT, 1.0f / OO, bias);
}

// ---------------------------------------------------------------------------
// Kernel 2: softmax over t for each (b,o). 160 blocks x 256 threads.
// ---------------------------------------------------------------------------
__global__ __launch_bounds__(256) void k_softmax() {
    const int ro = blockIdx.x;
    const int tid = threadIdx.x;
    const float4 v = ((const float4*)&g_scores[ro * TT])[tid];

    __shared__ float red[8];

    float m = fmaxf(fmaxf(v.x, v.y), fmaxf(v.z, v.w));
    #pragma unroll
    for (int s = 16; s > 0; s >>= 1)
        m = fmaxf(m, __shfl_xor_sync(0xffffffffu, m, s));
    if ((tid & 31) == 0) red[tid >> 5] = m;
    __syncthreads();
    float mall = red[0];
    #pragma unroll
    for (int i = 1; i < 8; i++) mall = fmaxf(mall, red[i]);
    __syncthreads();

    float4 e;
    e.x = __expf(v.x - mall);
    e.y = __expf(v.y - mall);
    e.z = __expf(v.z - mall);
    e.w = __expf(v.w - mall);
    float s4 = e.x + e.y + e.z + e.w;
    #pragma unroll
    for (int s = 16; s > 0; s >>= 1)
        s4 += __shfl_xor_sync(0xffffffffu, s4, s);
    if ((tid & 31) == 0) red[tid >> 5] = s4;
    __syncthreads();
    float sall = 0.0f;
    #pragma unroll
    for (int i = 0; i < 8; i++) sall += red[i];

    const float inv = 1.0f / sall;
    float4 w;
    w.x = e.x * inv; w.y = e.y * inv; w.z = e.z * inv; w.w = e.w * inv;
    ((float4*)&g_wx[ro * TT])[tid] = w;
}

// ---------------------------------------------------------------------------
// Kernel 3: out[b][o][t] = sum_i logits[b,t,i] * g_wx[b][o][i]
// ---------------------------------------------------------------------------
__global__ __launch_bounds__(CTA, 2) void k_out(const float* __restrict__ logits,
                                                float* __restrict__ out) {
    __shared__ float Wsm[W_FLOATS];

    const int row0blk = blockIdx.x * RPC;
    const int b = row0blk / TT;               // 32 rows never cross a batch
    {
        const float4* Wv = (const float4*)(g_wx + (size_t)b * W_FLOATS);
        float4* Ws = (float4*)Wsm;
        #pragma unroll
        for (int t = 0; t < 10; t++)
            Ws[threadIdx.x + t * CTA] = Wv[threadIdx.x + t * CTA];
    }
    __syncthreads();

    const int warp = threadIdx.x >> 5;
    const int lane = threadIdx.x & 31;
    const int row0 = row0blk + warp * RPW;

    ull acc[RPW][OO];
    gemv_body(logits + (size_t)row0 * DD + lane * 4, Wsm + lane * 4, acc);

    reduce_store(acc, lane, out + b * OO * TT, row0 % TT, 1.0f, nullptr);
}

// ---------------------------------------------------------------------------
// Launch: inputs per metadata order: logits, decision(unused), W, b
// ---------------------------------------------------------------------------
extern "C" void kernel_launch(void* const* d_in, const int* in_sizes, int n_in,
                              void* d_out, int out_size) {
    const float* logits = (const float*)d_in[0];
    const float* W = (const float*)d_in[2];
    const float* bias = (const float*)d_in[3];
    float* out = (float*)d_out;

    k_scores<<<(BB * TT) / RPC, CTA>>>(logits, W, bias);
    k_softmax<<<BB * OO, 256>>>();
    k_out<<<(BB * TT) / RPC, CTA>>>(logits, out);
}